// round 15
// baseline (speedup 1.0000x reference)
#include <cuda_runtime.h>
#include <cuda_bf16.h>
#include <math.h>
#include <float.h>

#define B_   32
#define NF_  196
#define ENC_ 2048
#define V_   32000
#define ED_  512
#define S_   32
#define H_   1024
#define NB_  128        // persistent grid size (all co-resident on 148 SMs)

// ---------------- f32x2 packed helpers (sm_103a) -----------------------------
__device__ __forceinline__ void fma2(unsigned long long& d,
                                     unsigned long long a, unsigned long long b) {
    asm("fma.rn.f32x2 %0, %1, %2, %0;" : "+l"(d) : "l"(a), "l"(b));
}
__device__ __forceinline__ unsigned long long pack2(float lo, float hi) {
    unsigned long long r;
    asm("mov.b64 %0, {%1, %2};" : "=l"(r) : "f"(lo), "f"(hi));
    return r;
}
__device__ __forceinline__ float2 unpk2(unsigned long long v) {
    float2 r;
    asm("mov.b64 {%0, %1}, %2;" : "=f"(r.x), "=f"(r.y) : "l"(v));
    return r;
}
__device__ __forceinline__ unsigned su32(const void* p) {
    return (unsigned)__cvta_generic_to_shared(p);
}
#define CP16(dst, src) \
    asm volatile("cp.async.cg.shared.global [%0], [%1], 16;" :: "r"(dst), "l"(src))
#define CPCOMMIT() asm volatile("cp.async.commit_group;")
#define CPWAIT(n)  asm volatile("cp.async.wait_group %0;" :: "n"(n))

// ---------------- scratch ----------------------------------------------------
static constexpr size_t SZ_K    = (size_t)B_ * NF_ * H_;
static constexpr size_t OFF_K   = 0;
static constexpr size_t OFF_V   = OFF_K + SZ_K;
static constexpr size_t OFF_MEAN= OFF_V + SZ_K;
static constexpr size_t OFF_H   = OFF_MEAN + (size_t)B_ * ENC_;
static constexpr size_t OFF_C   = OFF_H   + (size_t)B_ * H_;
static constexpr size_t OFF_Q   = OFF_C   + (size_t)B_ * H_;
static constexpr size_t OFF_CTX = OFF_Q   + (size_t)B_ * H_;
static constexpr size_t OFF_O   = OFF_CTX + (size_t)B_ * H_;
static constexpr size_t OFF_SC  = OFF_O   + (size_t)B_ * H_;
static constexpr size_t OFF_XP  = OFF_SC  + (size_t)B_ * 256;
static constexpr size_t OFF_AD  = OFF_XP  + (size_t)B_ * S_ * 4 * H_;
// bf16 hi/lo regions (sizes in floats = u16count/2; all multiples of 4)
static constexpr size_t OFF_FH  = OFF_AD  + (size_t)B_ * S_ * NF_;
static constexpr size_t SZ_F2   = (size_t)B_ * NF_ * ENC_ / 2;
static constexpr size_t OFF_FL  = OFF_FH  + SZ_F2;
static constexpr size_t OFF_KWH = OFF_FL  + SZ_F2;
static constexpr size_t SZ_KW2  = (size_t)H_ * ENC_ / 2;
static constexpr size_t OFF_KWL = OFF_KWH + SZ_KW2;
static constexpr size_t OFF_VWH = OFF_KWL + SZ_KW2;
static constexpr size_t OFF_VWL = OFF_VWH + SZ_KW2;
static constexpr size_t OFF_WIH = OFF_VWL + SZ_KW2;
static constexpr size_t SZ_WI2  = (size_t)4 * H_ * ED_ / 2;
static constexpr size_t OFF_WIL = OFF_WIH + SZ_WI2;
static constexpr size_t OFF_LWH = OFF_WIL + SZ_WI2;
static constexpr size_t SZ_LW2  = (size_t)V_ * H_ / 2;
static constexpr size_t OFF_LWL = OFF_LWH + SZ_LW2;
static constexpr size_t OFF_EBH = OFF_LWL + SZ_LW2;
static constexpr size_t SZ_EB2  = (size_t)B_ * S_ * ED_ / 2;
static constexpr size_t OFF_EBL = OFF_EBH + SZ_EB2;
static constexpr size_t OFF_HLH = OFF_EBL + SZ_EB2;
static constexpr size_t SZ_HL2  = (size_t)B_ * S_ * H_ / 2;
static constexpr size_t OFF_HLL = OFF_HLH + SZ_HL2;
static constexpr size_t TOTAL_F = OFF_HLL + SZ_HL2;

__device__ float g_scratch[TOTAL_F];
__device__ unsigned g_flags[NB_];
__device__ unsigned g_gen2 = 0;

// ---------------- grid-wide barrier (flag-array, replay-safe) ----------------
// Each block owns g_flags[bx]; block 0's threads spin one-flag-per-thread,
// then block 0 publishes g_gen2. Generations are monotonic across graph
// replays; the base is read from g_gen2 at kernel entry (quiesced value).
__device__ __forceinline__ void grid_bar2(unsigned next, int bx, int tid) {
    __syncthreads();
    if (bx == 0) {
        if (tid >= 1 && tid < NB_) {
            while (*(volatile unsigned*)&g_flags[tid] < next) __nanosleep(32);
            __threadfence();
        }
        __syncthreads();
        if (tid == 0) {
            __threadfence();
            *(volatile unsigned*)&g_gen2 = next;
        }
    } else {
        if (tid == 0) {
            __threadfence();
            *(volatile unsigned*)&g_flags[bx] = next;
            while (*(volatile unsigned*)&g_gen2 < next) __nanosleep(32);
            __threadfence();
        }
        __syncthreads();
    }
}

// ---------------- bf16 hi/lo convert core ------------------------------------
__device__ __forceinline__ void cvt8v(
    float4 x0, float4 x1, unsigned* dh, unsigned* dl)
{
    unsigned h[4], l[4];
    asm("cvt.rn.bf16x2.f32 %0, %1, %2;" : "=r"(h[0]) : "f"(x0.y), "f"(x0.x));
    asm("cvt.rn.bf16x2.f32 %0, %1, %2;" : "=r"(h[1]) : "f"(x0.w), "f"(x0.z));
    asm("cvt.rn.bf16x2.f32 %0, %1, %2;" : "=r"(h[2]) : "f"(x1.y), "f"(x1.x));
    asm("cvt.rn.bf16x2.f32 %0, %1, %2;" : "=r"(h[3]) : "f"(x1.w), "f"(x1.z));
    float r0 = x0.x - __uint_as_float(h[0] << 16);
    float r1 = x0.y - __uint_as_float(h[0] & 0xffff0000u);
    float r2 = x0.z - __uint_as_float(h[1] << 16);
    float r3 = x0.w - __uint_as_float(h[1] & 0xffff0000u);
    float r4 = x1.x - __uint_as_float(h[2] << 16);
    float r5 = x1.y - __uint_as_float(h[2] & 0xffff0000u);
    float r6 = x1.z - __uint_as_float(h[3] << 16);
    float r7 = x1.w - __uint_as_float(h[3] & 0xffff0000u);
    asm("cvt.rn.bf16x2.f32 %0, %1, %2;" : "=r"(l[0]) : "f"(r1), "f"(r0));
    asm("cvt.rn.bf16x2.f32 %0, %1, %2;" : "=r"(l[1]) : "f"(r3), "f"(r2));
    asm("cvt.rn.bf16x2.f32 %0, %1, %2;" : "=r"(l[2]) : "f"(r5), "f"(r4));
    asm("cvt.rn.bf16x2.f32 %0, %1, %2;" : "=r"(l[3]) : "f"(r7), "f"(r6));
    *(uint4*)dh = make_uint4(h[0], h[1], h[2], h[3]);
    *(uint4*)dl = make_uint4(l[0], l[1], l[2], l[3]);
}

// ---------------- elementwise split: fp32 -> bf16 hi/lo ----------------------
__global__ __launch_bounds__(256) void split_bf16(
    const float* __restrict__ in,
    unsigned short* __restrict__ hi, unsigned short* __restrict__ lo)
{
    size_t i = ((size_t)blockIdx.x * 256 + threadIdx.x) * 8;
    float4 x0 = *(const float4*)(in + i);
    float4 x1 = *(const float4*)(in + i + 4);
    cvt8v(x0, x1, (unsigned*)(hi + i), (unsigned*)(lo + i));
}

// ---------------- mean over N + exact gelu -----------------------------------
__global__ __launch_bounds__(256) void mean_gelu_kernel(
    const float* __restrict__ feat, float* __restrict__ outMean)
{
    int b = blockIdx.y;
    int e = blockIdx.x * 256 + threadIdx.x;
    const float* p = feat + (size_t)b * NF_ * ENC_ + e;
    float s = 0.f;
    #pragma unroll 4
    for (int n = 0; n < NF_; n++) s += p[(size_t)n * ENC_];
    s *= (1.0f / (float)NF_);
    outMean[(size_t)b * ENC_ + e] = 0.5f * s * (1.0f + erff(s * 0.70710678118654752f));
}

// ---------------- embedding gather (emits bf16 hi/lo) ------------------------
__global__ __launch_bounds__(256) void gather_kernel(
    const float* __restrict__ emb, const int* __restrict__ cap,
    unsigned short* __restrict__ outH, unsigned short* __restrict__ outL)
{
    int idx = blockIdx.x * 256 + threadIdx.x;
    int d  = idx & (ED_ - 1);
    int bs = idx >> 9;
    float v = emb[(size_t)cap[bs] * ED_ + d];
    __nv_bfloat16 hb = __float2bfloat16(v);
    float hf = __bfloat162float(hb);
    __nv_bfloat16 lb = __float2bfloat16(v - hf);
    outH[idx] = *(unsigned short*)&hb;
    outL[idx] = *(unsigned short*)&lb;
}

// ---------------- batched GEMV for M=32 (setup h0/c0 only) -------------------
__global__ __launch_bounds__(256) void gemvM32(
    const float* __restrict__ A, const float* __restrict__ W,
    const float* __restrict__ bias, float* __restrict__ C, int ldc, int K)
{
    __shared__ float sA[32][64];
    int tid = threadIdx.x, lane = tid & 31, w = tid >> 5;
    int n = blockIdx.x * 8 + w;
    const float* Wn = W + (size_t)n * K;
    float acc[32];
    #pragma unroll
    for (int b = 0; b < 32; b++) acc[b] = 0.f;
    for (int k0 = 0; k0 < K; k0 += 64) {
        __syncthreads();
        int kk = tid & 63, bb = tid >> 6;
        #pragma unroll
        for (int i = 0; i < 8; i++)
            sA[bb + i * 4][kk] = A[(size_t)(bb + i * 4) * K + k0 + kk];
        __syncthreads();
        float w0 = Wn[k0 + lane], w1 = Wn[k0 + 32 + lane];
        #pragma unroll
        for (int b = 0; b < 32; b++)
            acc[b] += w0 * sA[b][lane] + w1 * sA[b][lane + 32];
    }
    float out = 0.f;
    #pragma unroll
    for (int b = 0; b < 32; b++) {
        float v = acc[b];
        #pragma unroll
        for (int o = 16; o; o >>= 1) v += __shfl_xor_sync(0xffffffffu, v, o);
        if (lane == b) out = v;
    }
    C[(size_t)lane * (size_t)ldc + n] = out + bias[n];
}

// ---------------- mma.sync bf16x3 GEMM, pre-split inputs, cp.async pipeline --
// C[M][N] = (Ah+Al)[M][K] @ (Bh+Bl)[N][K]^T + bias  (fp32 accum, al*bl dropped)
// block: 256 thr = 8 warps (4M x 2N); tile 128x64; K-chunk 32 bf16.
#define MMA16816(d, a, b) \
    asm volatile("mma.sync.aligned.m16n8k16.row.col.f32.bf16.bf16.f32 " \
        "{%0,%1,%2,%3}, {%4,%5,%6,%7}, {%8,%9}, {%0,%1,%2,%3};" \
        : "+f"((d)[0]), "+f"((d)[1]), "+f"((d)[2]), "+f"((d)[3]) \
        : "r"((a)[0]), "r"((a)[1]), "r"((a)[2]), "r"((a)[3]), \
          "r"((b)[0]), "r"((b)[1]))

extern __shared__ float dsm[];

// dynamic smem layout (u32 idx): sAh[2][2560] sAl[2][2560] sBh[2][1280] sBl[2][1280]
#define SM_AH(buf) ((buf) * 2560)
#define SM_AL(buf) (5120 + (buf) * 2560)
#define SM_BH(buf) (10240 + (buf) * 1280)
#define SM_BL(buf) (12800 + (buf) * 1280)
#define MMA_SMEM_BYTES (15360 * 4)

__global__ __launch_bounds__(256, 3) void mma_gemm_bf16(
    const unsigned short* __restrict__ Ah, const unsigned short* __restrict__ Al,
    int lda,
    const unsigned short* __restrict__ Bh, const unsigned short* __restrict__ Bl,
    const float* __restrict__ bias,
    float* __restrict__ C, int ldc, int K)
{
    unsigned* smu = (unsigned*)dsm;
    unsigned smb = su32(smu);

    int tid = threadIdx.x, lane = tid & 31, wid = tid >> 5;
    int wm = wid & 3, wn = wid >> 2;
    int g = lane >> 2, tig = lane & 3;
    int m0 = blockIdx.y * 128, n0 = blockIdx.x * 64;

    float acc[2][4][4];
    #pragma unroll
    for (int mt = 0; mt < 2; mt++)
        #pragma unroll
        for (int nt = 0; nt < 4; nt++)
            #pragma unroll
            for (int i = 0; i < 4; i++) acc[mt][nt][i] = 0.f;

    // cp.async coords: A rows 128 x 16 b32 (4 chunks/row), 2 chunks/thread
    int arow = tid >> 1, aq2 = (tid & 1) * 2;       // quads aq2, aq2+1
    int brow = tid >> 2, bq = tid & 3;              // 1 chunk/thread

    const unsigned short* Ah0 = Ah + (size_t)(m0 + arow) * lda;
    const unsigned short* Al0 = Al + (size_t)(m0 + arow) * lda;
    const unsigned short* Bh0 = Bh + (size_t)(n0 + brow) * K;
    const unsigned short* Bl0 = Bl + (size_t)(n0 + brow) * K;

    auto load_tile = [&](int c, int buf) {
        int kb = c * 32;
        unsigned da = smb + (SM_AH(buf) + arow * 20 + aq2 * 4) * 4;
        unsigned dal = smb + (SM_AL(buf) + arow * 20 + aq2 * 4) * 4;
        const unsigned short* sa = Ah0 + kb + aq2 * 8;
        const unsigned short* sal = Al0 + kb + aq2 * 8;
        CP16(da, sa);
        CP16(da + 16, sa + 8);
        CP16(dal, sal);
        CP16(dal + 16, sal + 8);
        CP16(smb + (SM_BH(buf) + brow * 20 + bq * 4) * 4, Bh0 + kb + bq * 8);
        CP16(smb + (SM_BL(buf) + brow * 20 + bq * 4) * 4, Bl0 + kb + bq * 8);
    };

    int nchunks = K >> 5;
    load_tile(0, 0);
    CPCOMMIT();

    int buf = 0;
    for (int c = 0; c < nchunks; c++) {
        if (c + 1 < nchunks) {
            load_tile(c + 1, buf ^ 1);
            CPCOMMIT();
            CPWAIT(1);
        } else {
            CPWAIT(0);
        }
        __syncthreads();
        const unsigned* pAh = smu + SM_AH(buf);
        const unsigned* pAl = smu + SM_AL(buf);
        const unsigned* pBh = smu + SM_BH(buf);
        const unsigned* pBl = smu + SM_BL(buf);
        #pragma unroll
        for (int ks = 0; ks < 2; ks++) {
            unsigned ah[2][4], al[2][4], bh[4][2], bl[4][2];
            #pragma unroll
            for (int mt = 0; mt < 2; mt++) {
                int r = wm * 32 + mt * 16 + g;
                int base = r * 20 + ks * 8 + tig;
                ah[mt][0] = pAh[base];
                ah[mt][1] = pAh[base + 160];
                ah[mt][2] = pAh[base + 4];
                ah[mt][3] = pAh[base + 164];
                al[mt][0] = pAl[base];
                al[mt][1] = pAl[base + 160];
                al[mt][2] = pAl[base + 4];
                al[mt][3] = pAl[base + 164];
            }
            #pragma unroll
            for (int nt = 0; nt < 4; nt++) {
                int n = wn * 32 + nt * 8 + g;
                int base = n * 20 + ks * 8 + tig;
                bh[nt][0] = pBh[base];
                bh[nt][1] = pBh[base + 4];
                bl[nt][0] = pBl[base];
                bl[nt][1] = pBl[base + 4];
            }
            #pragma unroll
            for (int mt = 0; mt < 2; mt++)
                #pragma unroll
                for (int nt = 0; nt < 4; nt++) {
                    MMA16816(acc[mt][nt], ah[mt], bh[nt]);
                    MMA16816(acc[mt][nt], ah[mt], bl[nt]);
                    MMA16816(acc[mt][nt], al[mt], bh[nt]);
                }
        }
        __syncthreads();
        buf ^= 1;
    }

    #pragma unroll
    for (int mt = 0; mt < 2; mt++) {
        int row = m0 + wm * 32 + mt * 16 + g;
        #pragma unroll
        for (int nt = 0; nt < 4; nt++) {
            int col = n0 + wn * 32 + nt * 8 + 2 * tig;
            float2 bb = *(const float2*)(bias + col);
            float2 r0 = make_float2(acc[mt][nt][0] + bb.x, acc[mt][nt][1] + bb.y);
            float2 r1 = make_float2(acc[mt][nt][2] + bb.x, acc[mt][nt][3] + bb.y);
            *(float2*)(C + (size_t)row * ldc + col)       = r0;
            *(float2*)(C + (size_t)(row + 8) * ldc + col) = r1;
        }
    }
}

// ---------------- persistent recurrence kernel -------------------------------
__device__ __forceinline__ void gemv_direct(
    const float* __restrict__ Ag, const float* sW,
    const float* __restrict__ bias, int n0,
    const float* __restrict__ addH,
    float* __restrict__ Cg, int tid)
{
    int lane = tid & 31, w = tid >> 5;
    unsigned long long acc[32];
    #pragma unroll
    for (int p = 0; p < 32; p++) acc[p] = 0ull;

    const float* xb = Ag + (size_t)(4 * w) * H_ + 4 * lane;
    #pragma unroll
    for (int c = 0; c < 8; c++) {
        ulonglong2 xv[4];
        #pragma unroll
        for (int b = 0; b < 4; b++)
            xv[b] = *(const ulonglong2*)(xb + (size_t)b * H_ + c * 128);
        #pragma unroll
        for (int n = 0; n < 8; n++) {
            ulonglong2 wv = *(const ulonglong2*)&sW[n * H_ + c * 128 + 4 * lane];
            #pragma unroll
            for (int b = 0; b < 4; b++) {
                fma2(acc[b * 8 + n], xv[b].x, wv.x);
                fma2(acc[b * 8 + n], xv[b].y, wv.y);
            }
        }
    }
    float outv = 0.f;
    #pragma unroll
    for (int p = 0; p < 32; p++) {
        float2 v = unpk2(acc[p]);
        float s = v.x + v.y;
        #pragma unroll
        for (int o = 16; o; o >>= 1) s += __shfl_xor_sync(0xffffffffu, s, o);
        if (lane == p) outv = s;
    }
    int bg = 4 * w + (lane >> 3);
    int ng = n0 + (lane & 7);
    float r = outv + bias[ng];
    if (addH) r += addH[(size_t)bg * H_ + ng];
    Cg[(size_t)bg * H_ + ng] = r;
}

__global__ __launch_bounds__(256, 1) void recurrence_kernel(
    const float* __restrict__ q_w,  const float* __restrict__ in_b,
    const float* __restrict__ out_w,const float* __restrict__ out_b,
    const float* __restrict__ w_hh, const float* __restrict__ b_hh,
    const float* __restrict__ ln_g, const float* __restrict__ ln_b2,
    const float* __restrict__ gK,   const float* __restrict__ gV,
    const float* __restrict__ gXp,
    float* gH, float* gC, float* gQ, float* gSc,
    float* gCtx, float* gO,
    unsigned short* gHallH, unsigned short* gHallL, float* attnb)
{
    __shared__ float sQ[1024];
    __shared__ float sProb[224];
    __shared__ float sred[8];
    __shared__ float sbc;
    __shared__ float sG[1024];
    __shared__ float sMu[32], sRs[32];
    __shared__ unsigned sBase;

    float* SQW  = dsm;
    float* SOW  = dsm + 8192;
    float* SWH  = dsm + 16384;
    float* SLNG = dsm + 49152;
    float* SLNB = dsm + 50176;

    int tid = threadIdx.x, lane = tid & 31, w = tid >> 5;
    int bx = blockIdx.x;
    int ab = bx >> 2, apart = bx & 3;   // attention: 4 blocks per batch

    if (tid == 0) sBase = *(volatile unsigned*)&g_gen2;

    for (int i = tid; i < 8192; i += 256) {
        SQW[i] = q_w [(size_t)bx * 8192 + i];
        SOW[i] = out_w[(size_t)bx * 8192 + i];
    }
    for (int g = 0; g < 4; g++)
        for (int i = tid; i < 8192; i += 256)
            SWH[g * 8192 + i] = w_hh[((size_t)g * H_ + bx * 8) * H_ + i];
    for (int i = tid; i < 1024; i += 256) {
        SLNG[i] = ln_g[i];
        SLNB[i] = ln_b2[i];
    }
    __syncthreads();
    unsigned bnum = 0;

    for (int t = 0; t < S_; t++) {
        // ---- P0: q = h @ q_w^T + in_b[:H] ----
        gemv_direct(gH, SQW, in_b, bx * 8, nullptr, gQ, tid);
        grid_bar2(sBase + (++bnum), bx, tid);

        // ---- P1a: scores (block covers 49 n of batch ab) ----
        {
            for (int i = tid; i < 1024; i += 256)
                sQ[i] = gQ[(size_t)ab * H_ + i];
            __syncthreads();
            for (int n = apart * 49 + w; n < apart * 49 + 49; n += 8) {
                const float* kp = gK + ((size_t)ab * NF_ + n) * H_;
                float s = 0.f;
                #pragma unroll
                for (int j = 0; j < 8; j++) {
                    float4 q4 = *(const float4*)&sQ[4 * lane + 128 * j];
                    float4 k4 = *(const float4*)(kp + 4 * lane + 128 * j);
                    s += q4.x*k4.x + q4.y*k4.y + q4.z*k4.z + q4.w*k4.w;
                }
                #pragma unroll
                for (int o = 16; o; o >>= 1) s += __shfl_xor_sync(0xffffffffu, s, o);
                if (lane == 0) gSc[ab * 256 + n] = s * 0.03125f;
            }
        }
        grid_bar2(sBase + (++bnum), bx, tid);

        // ---- P1b: softmax (redundant x4) + ctx (block covers 256 h) ----
        {
            float v = (tid < NF_) ? gSc[ab * 256 + tid] : -FLT_MAX;
            float m = v;
            #pragma unroll
            for (int o = 16; o; o >>= 1) m = fmaxf(m, __shfl_xor_sync(0xffffffffu, m, o));
            if (lane == 0) sred[w] = m;
            __syncthreads();
            if (tid == 0) {
                float mm = sred[0];
                #pragma unroll
                for (int i = 1; i < 8; i++) mm = fmaxf(mm, sred[i]);
                sbc = mm;
            }
            __syncthreads();
            float e = (tid < NF_) ? expf(v - sbc) : 0.f;
            float s2 = e;
            #pragma unroll
            for (int o = 16; o; o >>= 1) s2 += __shfl_xor_sync(0xffffffffu, s2, o);
            if (lane == 0) sred[w] = s2;
            __syncthreads();
            if (tid == 0) {
                float ss = 0.f;
                #pragma unroll
                for (int i = 0; i < 8; i++) ss += sred[i];
                sbc = ss;
            }
            __syncthreads();
            float p = e / sbc;
            if (tid < NF_) {
                sProb[tid] = p;
                if (apart == 0)
                    attnb[((size_t)ab * S_ + t) * NF_ + tid] = p;
            }
            __syncthreads();
            {
                int h = apart * 256 + tid;
                const float* vb = gV + (size_t)ab * NF_ * H_ + h;
                float a = 0.f;
                #pragma unroll 1
                for (int n0b = 0; n0b < 192; n0b += 8) {
                    float vv[8];
                    #pragma unroll
                    for (int j = 0; j < 8; j++)
                        vv[j] = vb[(size_t)(n0b + j) * H_];
                    #pragma unroll
                    for (int j = 0; j < 8; j++)
                        a += sProb[n0b + j] * vv[j];
                }
                #pragma unroll
                for (int j = 0; j < 4; j++)
                    a += sProb[192 + j] * vb[(size_t)(192 + j) * H_];
                gCtx[(size_t)ab * H_ + h] = a;
            }
        }
        grid_bar2(sBase + (++bnum), bx, tid);

        // ---- P3: x = h + ctx @ out_w^T + out_b ----
        gemv_direct(gCtx, SOW, out_b, bx * 8, gH, gO, tid);
        grid_bar2(sBase + (++bnum), bx, tid);

        // ---- P5: LN (on the fly) + gates + LSTM ----
        {
            {
                int b = tid >> 3, sl = tid & 7;
                const float* xb = gO + (size_t)b * H_ + sl * 4;
                float s = 0.f, s2 = 0.f;
                #pragma unroll 8
                for (int i = 0; i < 32; i++) {
                    float4 v = *(const float4*)(xb + i * 32);
                    s  += v.x + v.y + v.z + v.w;
                    s2 += v.x*v.x + v.y*v.y + v.z*v.z + v.w*v.w;
                }
                #pragma unroll
                for (int o2 = 1; o2 < 8; o2 <<= 1) {
                    s  += __shfl_xor_sync(0xffffffffu, s,  o2);
                    s2 += __shfl_xor_sync(0xffffffffu, s2, o2);
                }
                if (sl == 0) {
                    float mu = s * (1.0f / H_);
                    float var = s2 * (1.0f / H_) - mu * mu;
                    sMu[b] = mu;
                    sRs[b] = rsqrtf(var + 1e-5f);
                }
            }
            __syncthreads();

            const float* xb = gO + (size_t)(4 * w) * H_ + 4 * lane;
            float muv[4], rsv[4];
            #pragma unroll
            for (int b = 0; b < 4; b++) {
                muv[b] = sMu[4 * w + b];
                rsv[b] = sRs[4 * w + b];
            }

            #pragma unroll 1
            for (int p2 = 0; p2 < 2; p2++) {
                int g0 = 2 * p2, g1 = 2 * p2 + 1;
                const float* W0 = SWH + (size_t)g0 * 8192;
                const float* W1 = SWH + (size_t)g1 * 8192;
                unsigned long long aA[32], aB[32];
                #pragma unroll
                for (int p = 0; p < 32; p++) { aA[p] = 0ull; aB[p] = 0ull; }

                #pragma unroll
                for (int c = 0; c < 8; c++) {
                    float4 g4 = *(const float4*)&SLNG[c * 128 + 4 * lane];
                    float4 b4 = *(const float4*)&SLNB[c * 128 + 4 * lane];
                    ulonglong2 xn[4];
                    #pragma unroll
                    for (int b = 0; b < 4; b++) {
                        float4 x = *(const float4*)(xb + (size_t)b * H_ + c * 128);
                        float mu = muv[b], rs = rsv[b];
                        float4 r;
                        r.x = (x.x - mu) * rs * g4.x + b4.x;
                        r.y = (x.y - mu) * rs * g4.y + b4.y;
                        r.z = (x.z - mu) * rs * g4.z + b4.z;
                        r.w = (x.w - mu) * rs * g4.w + b4.w;
                        xn[b].x = pack2(r.x, r.y);
                        xn[b].y = pack2(r.z, r.w);
                    }
                    #pragma unroll
                    for (int n = 0; n < 8; n++) {
                        ulonglong2 w0 = *(const ulonglong2*)&W0[n * H_ + c * 128 + 4 * lane];
                        ulonglong2 w1 = *(const ulonglong2*)&W1[n * H_ + c * 128 + 4 * lane];
                        #pragma unroll
                        for (int b = 0; b < 4; b++) {
                            fma2(aA[b * 8 + n], xn[b].x, w0.x);
                            fma2(aA[b * 8 + n], xn[b].y, w0.y);
                            fma2(aB[b * 8 + n], xn[b].x, w1.x);
                            fma2(aB[b * 8 + n], xn[b].y, w1.y);
                        }
                    }
                }
                float oA = 0.f, oB = 0.f;
                #pragma unroll
                for (int p = 0; p < 32; p++) {
                    float2 va = unpk2(aA[p]);
                    float2 vb = unpk2(aB[p]);
                    float sa = va.x + va.y, sb2 = vb.x + vb.y;
                    #pragma unroll
                    for (int o = 16; o; o >>= 1) {
                        sa  += __shfl_xor_sync(0xffffffffu, sa,  o);
                        sb2 += __shfl_xor_sync(0xffffffffu, sb2, o);
                    }
                    if (lane == p) { oA = sa; oB = sb2; }
                }
                int bg = 4 * w + (lane >> 3);
                int c  = lane & 7;
                int nA = g0 * H_ + bx * 8 + c;
                int nB = g1 * H_ + bx * 8 + c;
                size_t xrow = ((size_t)bg * S_ + t) * (4 * H_);
                oA += b_hh[nA] + gXp[xrow + nA];
                oB += b_hh[nB] + gXp[xrow + nB];
                sG[g0 * 256 + c * 32 + bg] = oA;
                sG[g1 * 256 + c * 32 + bg] = oB;
            }
            __syncthreads();
            int b = tid & 31, jj = tid >> 5;
            int j2 = bx * 8 + jj;
            float ii = sG[0 * 256 + jj * 32 + b];
            float ff = sG[1 * 256 + jj * 32 + b];
            float gg = sG[2 * 256 + jj * 32 + b];
            float oo = sG[3 * 256 + jj * 32 + b];
            float si = 1.f / (1.f + expf(-ii));
            float sf = 1.f / (1.f + expf(-ff));
            float so = 1.f / (1.f + expf(-oo));
            float cn = sf * gC[b * H_ + j2] + si * tanhf(gg);
            float hn = so * tanhf(cn);
            gC[b * H_ + j2] = cn;
            gH[b * H_ + j2] = hn;
            // store h as bf16 hi/lo for the logits GEMM
            size_t hidx = ((size_t)b * S_ + t) * H_ + j2;
            __nv_bfloat16 hb = __float2bfloat16(hn);
            float hf = __bfloat162float(hb);
            __nv_bfloat16 lb = __float2bfloat16(hn - hf);
            gHallH[hidx] = *(unsigned short*)&hb;
            gHallL[hidx] = *(unsigned short*)&lb;
        }
        grid_bar2(sBase + (++bnum), bx, tid);
    }
}

// ---------------- orchestration ----------------------------------------------
extern "C" void kernel_launch(void* const* d_in, const int* in_sizes, int n_in,
                              void* d_out, int out_size)
{
    const float* features = (const float*)d_in[0];
    const int*   captions = (const int*)  d_in[1];
    const float* emb      = (const float*)d_in[2];
    const float* q_w      = (const float*)d_in[3];
    const float* k_w      = (const float*)d_in[4];
    const float* v_w      = (const float*)d_in[5];
    const float* in_b     = (const float*)d_in[6];
    const float* out_w    = (const float*)d_in[7];
    const float* out_b    = (const float*)d_in[8];
    const float* h0_w     = (const float*)d_in[9];
    const float* h0_b     = (const float*)d_in[10];
    const float* c0_w     = (const float*)d_in[11];
    const float* c0_b     = (const float*)d_in[12];
    const float* w_ih     = (const float*)d_in[13];
    const float* b_ih     = (const float*)d_in[14];
    const float* w_hh     = (const float*)d_in[15];
    const float* b_hh     = (const float*)d_in[16];
    const float* ln_g     = (const float*)d_in[17];
    const float* ln_b2    = (const float*)d_in[18];
    const float* lin_w    = (const float*)d_in[19];
    const float* lin_b    = (const float*)d_in[20];

    float* sc = nullptr;
    cudaGetSymbolAddress((void**)&sc, g_scratch);
    float* gK    = sc + OFF_K;
    float* gV    = sc + OFF_V;
    float* gMean = sc + OFF_MEAN;
    float* gH    = sc + OFF_H;
    float* gC    = sc + OFF_C;
    float* gQ    = sc + OFF_Q;
    float* gCtx  = sc + OFF_CTX;
    float* gO    = sc + OFF_O;
    float* gSc   = sc + OFF_SC;
    float* gXp   = sc + OFF_XP;
    float* gAd   = sc + OFF_AD;
    unsigned short* gFH  = (unsigned short*)(sc + OFF_FH);
    unsigned short* gFL  = (unsigned short*)(sc + OFF_FL);
    unsigned short* gKWH = (unsigned short*)(sc + OFF_KWH);
    unsigned short* gKWL = (unsigned short*)(sc + OFF_KWL);
    unsigned short* gVWH = (unsigned short*)(sc + OFF_VWH);
    unsigned short* gVWL = (unsigned short*)(sc + OFF_VWL);
    unsigned short* gWIH = (unsigned short*)(sc + OFF_WIH);
    unsigned short* gWIL = (unsigned short*)(sc + OFF_WIL);
    unsigned short* gLWH = (unsigned short*)(sc + OFF_LWH);
    unsigned short* gLWL = (unsigned short*)(sc + OFF_LWL);
    unsigned short* gEBH = (unsigned short*)(sc + OFF_EBH);
    unsigned short* gEBL = (unsigned short*)(sc + OFF_EBL);
    unsigned short* gHLH = (unsigned short*)(sc + OFF_HLH);
    unsigned short* gHLL = (unsigned short*)(sc + OFF_HLL);

    float* out   = (float*)d_out;
    float* preds = out;
    const size_t PRED = (size_t)B_ * S_ * V_;
    bool wa = ((size_t)out_size >= PRED + (size_t)B_ * S_ * NF_);
    float* attnb = wa ? (out + PRED) : gAd;

    const int REC_SMEM = 51200 * 4;   // 200 KB for recurrence
    cudaFuncSetAttribute(recurrence_kernel,
                         cudaFuncAttributeMaxDynamicSharedMemorySize, REC_SMEM);
    cudaFuncSetAttribute(mma_gemm_bf16,
                         cudaFuncAttributeMaxDynamicSharedMemorySize, MMA_SMEM_BYTES);

    // ---- one-time bf16 hi/lo splits ----
    split_bf16<<<(B_ * NF_ * ENC_) / 2048, 256>>>(features, gFH, gFL);
    split_bf16<<<(H_ * ENC_) / 2048, 256>>>(k_w, gKWH, gKWL);
    split_bf16<<<(H_ * ENC_) / 2048, 256>>>(v_w, gVWH, gVWL);
    split_bf16<<<(4 * H_ * ED_) / 2048, 256>>>(w_ih, gWIH, gWIL);
    split_bf16<<<(V_ * H_) / 2048, 256>>>(lin_w, gLWH, gLWL);

    // ---- setup (hoisted) ----
    mean_gelu_kernel<<<dim3(ENC_ / 256, B_), 256>>>(features, gMean);
    gemvM32<<<H_ / 8, 256>>>(gMean, h0_w, h0_b, gH, H_, ENC_);
    gemvM32<<<H_ / 8, 256>>>(gMean, c0_w, c0_b, gC, H_, ENC_);
    mma_gemm_bf16<<<dim3(H_ / 64, (B_ * NF_) / 128), 256, MMA_SMEM_BYTES>>>(
        gFH, gFL, ENC_, gKWH, gKWL, in_b + H_,     gK, H_, ENC_);
    mma_gemm_bf16<<<dim3(H_ / 64, (B_ * NF_) / 128), 256, MMA_SMEM_BYTES>>>(
        gFH, gFL, ENC_, gVWH, gVWL, in_b + 2 * H_, gV, H_, ENC_);
    gather_kernel<<<(B_ * S_ * ED_) / 256, 256>>>(emb, captions, gEBH, gEBL);
    mma_gemm_bf16<<<dim3((4 * H_) / 64, (B_ * S_) / 128), 256, MMA_SMEM_BYTES>>>(
        gEBH, gEBL, ED_, gWIH, gWIL, b_ih, gXp, 4 * H_, ED_);

    // ---- recurrence in one persistent kernel ----
    recurrence_kernel<<<NB_, 256, REC_SMEM>>>(
        q_w, in_b, out_w, out_b, w_hh, b_hh, ln_g, ln_b2,
        gK, gV, gXp, gH, gC, gQ, gSc, gCtx, gO, gHLH, gHLL, attnb);

    // ---- batched logits on tensor cores ----
    mma_gemm_bf16<<<dim3(V_ / 64, (B_ * S_) / 128), 256, MMA_SMEM_BYTES>>>(
        gHLH, gHLL, H_, gLWH, gLWL, lin_b, preds, V_, H_);
}

// round 16
// speedup vs baseline: 1.0498x; 1.0498x over previous
#include <cuda_runtime.h>
#include <cuda_bf16.h>
#include <math.h>
#include <float.h>

#define B_   32
#define NF_  196
#define ENC_ 2048
#define V_   32000
#define ED_  512
#define S_   32
#define H_   1024
#define NB_  128        // persistent grid size (all co-resident on 148 SMs)

// ---------------- f32x2 packed helpers (sm_103a) -----------------------------
__device__ __forceinline__ void fma2(unsigned long long& d,
                                     unsigned long long a, unsigned long long b) {
    asm("fma.rn.f32x2 %0, %1, %2, %0;" : "+l"(d) : "l"(a), "l"(b));
}
__device__ __forceinline__ unsigned long long pack2(float lo, float hi) {
    unsigned long long r;
    asm("mov.b64 %0, {%1, %2};" : "=l"(r) : "f"(lo), "f"(hi));
    return r;
}
__device__ __forceinline__ float2 unpk2(unsigned long long v) {
    float2 r;
    asm("mov.b64 {%0, %1}, %2;" : "=f"(r.x), "=f"(r.y) : "l"(v));
    return r;
}
__device__ __forceinline__ unsigned su32(const void* p) {
    return (unsigned)__cvta_generic_to_shared(p);
}
#define CP16(dst, src) \
    asm volatile("cp.async.cg.shared.global [%0], [%1], 16;" :: "r"(dst), "l"(src))
#define CPCOMMIT() asm volatile("cp.async.commit_group;")
#define CPWAIT(n)  asm volatile("cp.async.wait_group %0;" :: "n"(n))

// ---------------- scratch ----------------------------------------------------
static constexpr size_t SZ_K    = (size_t)B_ * NF_ * H_;
static constexpr size_t OFF_K   = 0;
static constexpr size_t OFF_V   = OFF_K + SZ_K;
static constexpr size_t OFF_MEAN= OFF_V + SZ_K;
static constexpr size_t OFF_H   = OFF_MEAN + (size_t)B_ * ENC_;
static constexpr size_t OFF_C   = OFF_H   + (size_t)B_ * H_;
static constexpr size_t OFF_Q   = OFF_C   + (size_t)B_ * H_;
static constexpr size_t OFF_CTX = OFF_Q   + (size_t)B_ * H_;
static constexpr size_t OFF_O   = OFF_CTX + (size_t)B_ * H_;
static constexpr size_t OFF_SC  = OFF_O   + (size_t)B_ * H_;
static constexpr size_t OFF_XP  = OFF_SC  + (size_t)B_ * 256;
static constexpr size_t OFF_AD  = OFF_XP  + (size_t)B_ * S_ * 4 * H_;
static constexpr size_t OFF_FH  = OFF_AD  + (size_t)B_ * S_ * NF_;
static constexpr size_t SZ_F2   = (size_t)B_ * NF_ * ENC_ / 2;
static constexpr size_t OFF_FL  = OFF_FH  + SZ_F2;
static constexpr size_t OFF_KWH = OFF_FL  + SZ_F2;
static constexpr size_t SZ_KW2  = (size_t)H_ * ENC_ / 2;
static constexpr size_t OFF_KWL = OFF_KWH + SZ_KW2;
static constexpr size_t OFF_VWH = OFF_KWL + SZ_KW2;
static constexpr size_t OFF_VWL = OFF_VWH + SZ_KW2;
static constexpr size_t OFF_WIH = OFF_VWL + SZ_KW2;
static constexpr size_t SZ_WI2  = (size_t)4 * H_ * ED_ / 2;
static constexpr size_t OFF_WIL = OFF_WIH + SZ_WI2;
static constexpr size_t OFF_LWH = OFF_WIL + SZ_WI2;
static constexpr size_t SZ_LW2  = (size_t)V_ * H_ / 2;
static constexpr size_t OFF_LWL = OFF_LWH + SZ_LW2;
static constexpr size_t OFF_EBH = OFF_LWL + SZ_LW2;
static constexpr size_t SZ_EB2  = (size_t)B_ * S_ * ED_ / 2;
static constexpr size_t OFF_EBL = OFF_EBH + SZ_EB2;
static constexpr size_t OFF_HLH = OFF_EBL + SZ_EB2;
static constexpr size_t SZ_HL2  = (size_t)B_ * S_ * H_ / 2;
static constexpr size_t OFF_HLL = OFF_HLH + SZ_HL2;
static constexpr size_t TOTAL_F = OFF_HLL + SZ_HL2;

__device__ float g_scratch[TOTAL_F];
__device__ unsigned g_bar_count = 0;
__device__ unsigned g_bar_gen   = 0;

// ---------------- grid-wide barrier (round-14 proven) ------------------------
__device__ __forceinline__ void grid_bar() {
    __syncthreads();
    if (threadIdx.x == 0) {
        __threadfence();
        unsigned gen = *(volatile unsigned*)&g_bar_gen;
        unsigned a = atomicAdd(&g_bar_count, 1u);
        if (a == NB_ - 1) {
            atomicExch(&g_bar_count, 0u);
            __threadfence();
            atomicAdd(&g_bar_gen, 1u);
        } else {
            while (*(volatile unsigned*)&g_bar_gen == gen) __nanosleep(64);
        }
        __threadfence();
    }
    __syncthreads();
}

// ---------------- bf16 hi/lo convert core ------------------------------------
__device__ __forceinline__ void cvt8v(
    float4 x0, float4 x1, unsigned* dh, unsigned* dl)
{
    unsigned h[4], l[4];
    asm("cvt.rn.bf16x2.f32 %0, %1, %2;" : "=r"(h[0]) : "f"(x0.y), "f"(x0.x));
    asm("cvt.rn.bf16x2.f32 %0, %1, %2;" : "=r"(h[1]) : "f"(x0.w), "f"(x0.z));
    asm("cvt.rn.bf16x2.f32 %0, %1, %2;" : "=r"(h[2]) : "f"(x1.y), "f"(x1.x));
    asm("cvt.rn.bf16x2.f32 %0, %1, %2;" : "=r"(h[3]) : "f"(x1.w), "f"(x1.z));
    float r0 = x0.x - __uint_as_float(h[0] << 16);
    float r1 = x0.y - __uint_as_float(h[0] & 0xffff0000u);
    float r2 = x0.z - __uint_as_float(h[1] << 16);
    float r3 = x0.w - __uint_as_float(h[1] & 0xffff0000u);
    float r4 = x1.x - __uint_as_float(h[2] << 16);
    float r5 = x1.y - __uint_as_float(h[2] & 0xffff0000u);
    float r6 = x1.z - __uint_as_float(h[3] << 16);
    float r7 = x1.w - __uint_as_float(h[3] & 0xffff0000u);
    asm("cvt.rn.bf16x2.f32 %0, %1, %2;" : "=r"(l[0]) : "f"(r1), "f"(r0));
    asm("cvt.rn.bf16x2.f32 %0, %1, %2;" : "=r"(l[1]) : "f"(r3), "f"(r2));
    asm("cvt.rn.bf16x2.f32 %0, %1, %2;" : "=r"(l[2]) : "f"(r5), "f"(r4));
    asm("cvt.rn.bf16x2.f32 %0, %1, %2;" : "=r"(l[3]) : "f"(r7), "f"(r6));
    *(uint4*)dh = make_uint4(h[0], h[1], h[2], h[3]);
    *(uint4*)dl = make_uint4(l[0], l[1], l[2], l[3]);
}

// ---------------- elementwise split: fp32 -> bf16 hi/lo ----------------------
__global__ __launch_bounds__(256) void split_bf16(
    const float* __restrict__ in,
    unsigned short* __restrict__ hi, unsigned short* __restrict__ lo)
{
    size_t i = ((size_t)blockIdx.x * 256 + threadIdx.x) * 8;
    float4 x0 = *(const float4*)(in + i);
    float4 x1 = *(const float4*)(in + i + 4);
    cvt8v(x0, x1, (unsigned*)(hi + i), (unsigned*)(lo + i));
}

// ---------------- mean over N + exact gelu -----------------------------------
__global__ __launch_bounds__(256) void mean_gelu_kernel(
    const float* __restrict__ feat, float* __restrict__ outMean)
{
    int b = blockIdx.y;
    int e = blockIdx.x * 256 + threadIdx.x;
    const float* p = feat + (size_t)b * NF_ * ENC_ + e;
    float s = 0.f;
    #pragma unroll 4
    for (int n = 0; n < NF_; n++) s += p[(size_t)n * ENC_];
    s *= (1.0f / (float)NF_);
    outMean[(size_t)b * ENC_ + e] = 0.5f * s * (1.0f + erff(s * 0.70710678118654752f));
}

// ---------------- embedding gather (emits bf16 hi/lo) ------------------------
__global__ __launch_bounds__(256) void gather_kernel(
    const float* __restrict__ emb, const int* __restrict__ cap,
    unsigned short* __restrict__ outH, unsigned short* __restrict__ outL)
{
    int idx = blockIdx.x * 256 + threadIdx.x;
    int d  = idx & (ED_ - 1);
    int bs = idx >> 9;
    float v = emb[(size_t)cap[bs] * ED_ + d];
    __nv_bfloat16 hb = __float2bfloat16(v);
    float hf = __bfloat162float(hb);
    __nv_bfloat16 lb = __float2bfloat16(v - hf);
    outH[idx] = *(unsigned short*)&hb;
    outL[idx] = *(unsigned short*)&lb;
}

// ---------------- batched GEMV for M=32 (setup h0/c0 only) -------------------
__global__ __launch_bounds__(256) void gemvM32(
    const float* __restrict__ A, const float* __restrict__ W,
    const float* __restrict__ bias, float* __restrict__ C, int ldc, int K)
{
    __shared__ float sA[32][64];
    int tid = threadIdx.x, lane = tid & 31, w = tid >> 5;
    int n = blockIdx.x * 8 + w;
    const float* Wn = W + (size_t)n * K;
    float acc[32];
    #pragma unroll
    for (int b = 0; b < 32; b++) acc[b] = 0.f;
    for (int k0 = 0; k0 < K; k0 += 64) {
        __syncthreads();
        int kk = tid & 63, bb = tid >> 6;
        #pragma unroll
        for (int i = 0; i < 8; i++)
            sA[bb + i * 4][kk] = A[(size_t)(bb + i * 4) * K + k0 + kk];
        __syncthreads();
        float w0 = Wn[k0 + lane], w1 = Wn[k0 + 32 + lane];
        #pragma unroll
        for (int b = 0; b < 32; b++)
            acc[b] += w0 * sA[b][lane] + w1 * sA[b][lane + 32];
    }
    float out = 0.f;
    #pragma unroll
    for (int b = 0; b < 32; b++) {
        float v = acc[b];
        #pragma unroll
        for (int o = 16; o; o >>= 1) v += __shfl_xor_sync(0xffffffffu, v, o);
        if (lane == b) out = v;
    }
    C[(size_t)lane * (size_t)ldc + n] = out + bias[n];
}

// ---------------- mma.sync bf16x3 GEMM, pre-split inputs, cp.async pipeline --
#define MMA16816(d, a, b) \
    asm volatile("mma.sync.aligned.m16n8k16.row.col.f32.bf16.bf16.f32 " \
        "{%0,%1,%2,%3}, {%4,%5,%6,%7}, {%8,%9}, {%0,%1,%2,%3};" \
        : "+f"((d)[0]), "+f"((d)[1]), "+f"((d)[2]), "+f"((d)[3]) \
        : "r"((a)[0]), "r"((a)[1]), "r"((a)[2]), "r"((a)[3]), \
          "r"((b)[0]), "r"((b)[1]))

extern __shared__ float dsm[];

#define SM_AH(buf) ((buf) * 2560)
#define SM_AL(buf) (5120 + (buf) * 2560)
#define SM_BH(buf) (10240 + (buf) * 1280)
#define SM_BL(buf) (12800 + (buf) * 1280)
#define MMA_SMEM_BYTES (15360 * 4)

__global__ __launch_bounds__(256) void mma_gemm_bf16(
    const unsigned short* __restrict__ Ah, const unsigned short* __restrict__ Al,
    int lda,
    const unsigned short* __restrict__ Bh, const unsigned short* __restrict__ Bl,
    const float* __restrict__ bias,
    float* __restrict__ C, int ldc, int K)
{
    unsigned* smu = (unsigned*)dsm;
    unsigned smb = su32(smu);

    int tid = threadIdx.x, lane = tid & 31, wid = tid >> 5;
    int wm = wid & 3, wn = wid >> 2;
    int g = lane >> 2, tig = lane & 3;
    int m0 = blockIdx.y * 128, n0 = blockIdx.x * 64;

    float acc[2][4][4];
    #pragma unroll
    for (int mt = 0; mt < 2; mt++)
        #pragma unroll
        for (int nt = 0; nt < 4; nt++)
            #pragma unroll
            for (int i = 0; i < 4; i++) acc[mt][nt][i] = 0.f;

    int arow = tid >> 1, aq2 = (tid & 1) * 2;
    int brow = tid >> 2, bq = tid & 3;

    const unsigned short* Ah0 = Ah + (size_t)(m0 + arow) * lda;
    const unsigned short* Al0 = Al + (size_t)(m0 + arow) * lda;
    const unsigned short* Bh0 = Bh + (size_t)(n0 + brow) * K;
    const unsigned short* Bl0 = Bl + (size_t)(n0 + brow) * K;

    auto load_tile = [&](int c, int buf) {
        int kb = c * 32;
        unsigned da = smb + (SM_AH(buf) + arow * 20 + aq2 * 4) * 4;
        unsigned dal = smb + (SM_AL(buf) + arow * 20 + aq2 * 4) * 4;
        const unsigned short* sa = Ah0 + kb + aq2 * 8;
        const unsigned short* sal = Al0 + kb + aq2 * 8;
        CP16(da, sa);
        CP16(da + 16, sa + 8);
        CP16(dal, sal);
        CP16(dal + 16, sal + 8);
        CP16(smb + (SM_BH(buf) + brow * 20 + bq * 4) * 4, Bh0 + kb + bq * 8);
        CP16(smb + (SM_BL(buf) + brow * 20 + bq * 4) * 4, Bl0 + kb + bq * 8);
    };

    int nchunks = K >> 5;
    load_tile(0, 0);
    CPCOMMIT();

    int buf = 0;
    for (int c = 0; c < nchunks; c++) {
        if (c + 1 < nchunks) {
            load_tile(c + 1, buf ^ 1);
            CPCOMMIT();
            CPWAIT(1);
        } else {
            CPWAIT(0);
        }
        __syncthreads();
        const unsigned* pAh = smu + SM_AH(buf);
        const unsigned* pAl = smu + SM_AL(buf);
        const unsigned* pBh = smu + SM_BH(buf);
        const unsigned* pBl = smu + SM_BL(buf);
        #pragma unroll
        for (int ks = 0; ks < 2; ks++) {
            unsigned ah[2][4], al[2][4], bh[4][2], bl[4][2];
            #pragma unroll
            for (int mt = 0; mt < 2; mt++) {
                int r = wm * 32 + mt * 16 + g;
                int base = r * 20 + ks * 8 + tig;
                ah[mt][0] = pAh[base];
                ah[mt][1] = pAh[base + 160];
                ah[mt][2] = pAh[base + 4];
                ah[mt][3] = pAh[base + 164];
                al[mt][0] = pAl[base];
                al[mt][1] = pAl[base + 160];
                al[mt][2] = pAl[base + 4];
                al[mt][3] = pAl[base + 164];
            }
            #pragma unroll
            for (int nt = 0; nt < 4; nt++) {
                int n = wn * 32 + nt * 8 + g;
                int base = n * 20 + ks * 8 + tig;
                bh[nt][0] = pBh[base];
                bh[nt][1] = pBh[base + 4];
                bl[nt][0] = pBl[base];
                bl[nt][1] = pBl[base + 4];
            }
            #pragma unroll
            for (int mt = 0; mt < 2; mt++)
                #pragma unroll
                for (int nt = 0; nt < 4; nt++) {
                    MMA16816(acc[mt][nt], ah[mt], bh[nt]);
                    MMA16816(acc[mt][nt], ah[mt], bl[nt]);
                    MMA16816(acc[mt][nt], al[mt], bh[nt]);
                }
        }
        __syncthreads();
        buf ^= 1;
    }

    #pragma unroll
    for (int mt = 0; mt < 2; mt++) {
        int row = m0 + wm * 32 + mt * 16 + g;
        #pragma unroll
        for (int nt = 0; nt < 4; nt++) {
            int col = n0 + wn * 32 + nt * 8 + 2 * tig;
            float2 bb = *(const float2*)(bias + col);
            float2 r0 = make_float2(acc[mt][nt][0] + bb.x, acc[mt][nt][1] + bb.y);
            float2 r1 = make_float2(acc[mt][nt][2] + bb.x, acc[mt][nt][3] + bb.y);
            *(float2*)(C + (size_t)row * ldc + col)       = r0;
            *(float2*)(C + (size_t)(row + 8) * ldc + col) = r1;
        }
    }
}

// ---------------- persistent recurrence kernel -------------------------------
// dynamic smem (float idx): SQW[0..8192) SOW[8192..16384)
//   SWHH u32 @16384 (32x516) SWHL u32 @32896 (32x516)
//   SLNG @49408 SLNB @50432  STGH u32 @51456 (32x36) STGL u32 @52608
//   total 53760 floats = 215,040 B
__device__ __forceinline__ void gemv_direct(
    const float* __restrict__ Ag, const float* sW,
    const float* __restrict__ bias, int n0,
    const float* __restrict__ addH,
    float* __restrict__ Cg, int tid)
{
    int lane = tid & 31, w = tid >> 5;
    unsigned long long acc[32];
    #pragma unroll
    for (int p = 0; p < 32; p++) acc[p] = 0ull;

    const float* xb = Ag + (size_t)(4 * w) * H_ + 4 * lane;
    #pragma unroll
    for (int c = 0; c < 8; c++) {
        ulonglong2 xv[4];
        #pragma unroll
        for (int b = 0; b < 4; b++)
            xv[b] = *(const ulonglong2*)(xb + (size_t)b * H_ + c * 128);
        #pragma unroll
        for (int n = 0; n < 8; n++) {
            ulonglong2 wv = *(const ulonglong2*)&sW[n * H_ + c * 128 + 4 * lane];
            #pragma unroll
            for (int b = 0; b < 4; b++) {
                fma2(acc[b * 8 + n], xv[b].x, wv.x);
                fma2(acc[b * 8 + n], xv[b].y, wv.y);
            }
        }
    }
    float outv = 0.f;
    #pragma unroll
    for (int p = 0; p < 32; p++) {
        float2 v = unpk2(acc[p]);
        float s = v.x + v.y;
        #pragma unroll
        for (int o = 16; o; o >>= 1) s += __shfl_xor_sync(0xffffffffu, s, o);
        if (lane == p) outv = s;
    }
    int bg = 4 * w + (lane >> 3);
    int ng = n0 + (lane & 7);
    float r = outv + bias[ng];
    if (addH) r += addH[(size_t)bg * H_ + ng];
    Cg[(size_t)bg * H_ + ng] = r;
}

__global__ __launch_bounds__(256, 1) void recurrence_kernel(
    const float* __restrict__ q_w,  const float* __restrict__ in_b,
    const float* __restrict__ out_w,const float* __restrict__ out_b,
    const float* __restrict__ w_hh, const float* __restrict__ b_hh,
    const float* __restrict__ ln_g, const float* __restrict__ ln_b2,
    const float* __restrict__ gK,   const float* __restrict__ gV,
    const float* __restrict__ gXp,
    float* gH, float* gC, float* gQ, float* gSc,
    float* gCtx, float* gO,
    unsigned short* gHallH, unsigned short* gHallL, float* attnb)
{
    __shared__ float sQ[1024];
    __shared__ float sProb[224];
    __shared__ float sred[8];
    __shared__ float sbc;
    __shared__ float sG[1024];
    __shared__ float sMu[32], sRs[32];

    float* SQW  = dsm;
    float* SOW  = dsm + 8192;
    unsigned* SWHH = (unsigned*)(dsm + 16384);
    unsigned* SWHL = (unsigned*)(dsm + 32896);
    float* SLNG = dsm + 49408;
    float* SLNB = dsm + 50432;
    unsigned* STGH = (unsigned*)(dsm + 51456);
    unsigned* STGL = (unsigned*)(dsm + 52608);

    int tid = threadIdx.x, lane = tid & 31, w = tid >> 5;
    int bx = blockIdx.x;
    int ab = bx >> 2, apart = bx & 3;   // attention: 4 blocks per batch

    for (int i = tid; i < 8192; i += 256) {
        SQW[i] = q_w [(size_t)bx * 8192 + i];
        SOW[i] = out_w[(size_t)bx * 8192 + i];
    }
    // w_hh slice -> bf16 hi/lo, rows n=0..31: global row (n>>3)*H + bx*8 + (n&7)
    for (int it = tid; it < 4096; it += 256) {
        int n = it >> 7;
        int koff = (it & 127) * 8;
        int grow = (n >> 3) * H_ + bx * 8 + (n & 7);
        const float* src = w_hh + (size_t)grow * H_ + koff;
        cvt8v(*(const float4*)src, *(const float4*)(src + 4),
              SWHH + n * 516 + koff / 2, SWHL + n * 516 + koff / 2);
    }
    for (int i = tid; i < 1024; i += 256) {
        SLNG[i] = ln_g[i];
        SLNB[i] = ln_b2[i];
    }
    __syncthreads();

    for (int t = 0; t < S_; t++) {
        // ---- P0: q = h @ q_w^T + in_b[:H] ----
        gemv_direct(gH, SQW, in_b, bx * 8, nullptr, gQ, tid);
        grid_bar();

        // ---- P1a: scores (block covers 49 n of batch ab) ----
        {
            for (int i = tid; i < 1024; i += 256)
                sQ[i] = gQ[(size_t)ab * H_ + i];
            __syncthreads();
            for (int n = apart * 49 + w; n < apart * 49 + 49; n += 8) {
                const float* kp = gK + ((size_t)ab * NF_ + n) * H_;
                float s = 0.f;
                #pragma unroll
                for (int j = 0; j < 8; j++) {
                    float4 q4 = *(const float4*)&sQ[4 * lane + 128 * j];
                    float4 k4 = *(const float4*)(kp + 4 * lane + 128 * j);
                    s += q4.x*k4.x + q4.y*k4.y + q4.z*k4.z + q4.w*k4.w;
                }
                #pragma unroll
                for (int o = 16; o; o >>= 1) s += __shfl_xor_sync(0xffffffffu, s, o);
                if (lane == 0) gSc[ab * 256 + n] = s * 0.03125f;
            }
        }
        grid_bar();

        // ---- P1b: softmax (redundant x4) + ctx (block covers 256 h) ----
        {
            float v = (tid < NF_) ? gSc[ab * 256 + tid] : -FLT_MAX;
            float m = v;
            #pragma unroll
            for (int o = 16; o; o >>= 1) m = fmaxf(m, __shfl_xor_sync(0xffffffffu, m, o));
            if (lane == 0) sred[w] = m;
            __syncthreads();
            if (tid == 0) {
                float mm = sred[0];
                #pragma unroll
                for (int i = 1; i < 8; i++) mm = fmaxf(mm, sred[i]);
                sbc = mm;
            }
            __syncthreads();
            float e = (tid < NF_) ? expf(v - sbc) : 0.f;
            float s2 = e;
            #pragma unroll
            for (int o = 16; o; o >>= 1) s2 += __shfl_xor_sync(0xffffffffu, s2, o);
            if (lane == 0) sred[w] = s2;
            __syncthreads();
            if (tid == 0) {
                float ss = 0.f;
                #pragma unroll
                for (int i = 0; i < 8; i++) ss += sred[i];
                sbc = ss;
            }
            __syncthreads();
            float p = e / sbc;
            if (tid < NF_) {
                sProb[tid] = p;
                if (apart == 0)
                    attnb[((size_t)ab * S_ + t) * NF_ + tid] = p;
            }
            __syncthreads();
            {
                int h = apart * 256 + tid;
                const float* vb = gV + (size_t)ab * NF_ * H_ + h;
                float a = 0.f;
                #pragma unroll 1
                for (int n0b = 0; n0b < 192; n0b += 8) {
                    float vv[8];
                    #pragma unroll
                    for (int j = 0; j < 8; j++)
                        vv[j] = vb[(size_t)(n0b + j) * H_];
                    #pragma unroll
                    for (int j = 0; j < 8; j++)
                        a += sProb[n0b + j] * vv[j];
                }
                #pragma unroll
                for (int j = 0; j < 4; j++)
                    a += sProb[192 + j] * vb[(size_t)(192 + j) * H_];
                gCtx[(size_t)ab * H_ + h] = a;
            }
        }
        grid_bar();

        // ---- P3: x = h + ctx @ out_w^T + out_b ----
        gemv_direct(gCtx, SOW, out_b, bx * 8, gH, gO, tid);
        grid_bar();

        // ---- P5: LN stats + gates on tensor cores + LSTM ----
        {
            // LN pre-pass: mu/rs for all 32 batches from x = gO
            {
                int b = tid >> 3, sl = tid & 7;
                const float* xb = gO + (size_t)b * H_ + sl * 4;
                float s = 0.f, s2 = 0.f;
                #pragma unroll 8
                for (int i = 0; i < 32; i++) {
                    float4 v = *(const float4*)(xb + i * 32);
                    s  += v.x + v.y + v.z + v.w;
                    s2 += v.x*v.x + v.y*v.y + v.z*v.z + v.w*v.w;
                }
                #pragma unroll
                for (int o2 = 1; o2 < 8; o2 <<= 1) {
                    s  += __shfl_xor_sync(0xffffffffu, s,  o2);
                    s2 += __shfl_xor_sync(0xffffffffu, s2, o2);
                }
                if (sl == 0) {
                    float mu = s * (1.0f / H_);
                    float var = s2 * (1.0f / H_) - mu * mu;
                    sMu[b] = mu;
                    sRs[b] = rsqrtf(var + 1e-5f);
                }
            }
            __syncthreads();

            int wm = w & 1, wn = w >> 1;           // warp grid 2(M) x 4(N=gates)
            int g = lane >> 2, tig = lane & 3;
            float acc4[4] = {0.f, 0.f, 0.f, 0.f};
            int sb = tid >> 3, sl = tid & 7;
            float mu = sMu[sb], rs = sRs[sb];

            #pragma unroll 1
            for (int kc = 0; kc < 16; kc++) {
                if (kc > 0) __syncthreads();       // staging reuse guard
                {
                    int k0 = kc * 64 + sl * 8;
                    const float* xp4 = gO + (size_t)sb * H_ + k0;
                    float4 x0 = *(const float4*)(xp4);
                    float4 x1 = *(const float4*)(xp4 + 4);
                    float4 g0v = *(const float4*)&SLNG[k0];
                    float4 g1v = *(const float4*)&SLNG[k0 + 4];
                    float4 b0v = *(const float4*)&SLNB[k0];
                    float4 b1v = *(const float4*)&SLNB[k0 + 4];
                    float4 y0, y1;
                    y0.x = (x0.x - mu) * rs * g0v.x + b0v.x;
                    y0.y = (x0.y - mu) * rs * g0v.y + b0v.y;
                    y0.z = (x0.z - mu) * rs * g0v.z + b0v.z;
                    y0.w = (x0.w - mu) * rs * g0v.w + b0v.w;
                    y1.x = (x1.x - mu) * rs * g1v.x + b1v.x;
                    y1.y = (x1.y - mu) * rs * g1v.y + b1v.y;
                    y1.z = (x1.z - mu) * rs * g1v.z + b1v.z;
                    y1.w = (x1.w - mu) * rs * g1v.w + b1v.w;
                    cvt8v(y0, y1, STGH + sb * 36 + sl * 4, STGL + sb * 36 + sl * 4);
                }
                __syncthreads();
                #pragma unroll
                for (int ks = 0; ks < 4; ks++) {
                    unsigned ah[4], al[4], bh2[2], bl2[2];
                    int abase = (wm * 16 + g) * 36 + ks * 8 + tig;
                    ah[0] = STGH[abase];       ah[1] = STGH[abase + 288];
                    ah[2] = STGH[abase + 4];   ah[3] = STGH[abase + 292];
                    al[0] = STGL[abase];       al[1] = STGL[abase + 288];
                    al[2] = STGL[abase + 4];   al[3] = STGL[abase + 292];
                    int bbase = (wn * 8 + g) * 516 + kc * 32 + ks * 8 + tig;
                    bh2[0] = SWHH[bbase];      bh2[1] = SWHH[bbase + 4];
                    bl2[0] = SWHL[bbase];      bl2[1] = SWHL[bbase + 4];
                    MMA16816(acc4, ah, bh2);
                    MMA16816(acc4, ah, bl2);
                    MMA16816(acc4, al, bh2);
                }
            }

            // epilogue: d0,d1 = batch wm*16+g cols 2tig,2tig+1; d2,d3 = batch +8
            {
                int c0 = 2 * tig, c1 = c0 + 1;
                int b1 = wm * 16 + g, b2 = b1 + 8;
                int nbase = wn * H_ + bx * 8;
                float biasA = b_hh[nbase + c0], biasB = b_hh[nbase + c1];
                size_t xr1 = ((size_t)b1 * S_ + t) * (4 * H_) + nbase;
                size_t xr2 = ((size_t)b2 * S_ + t) * (4 * H_) + nbase;
                sG[wn * 256 + c0 * 32 + b1] = acc4[0] + biasA + gXp[xr1 + c0];
                sG[wn * 256 + c1 * 32 + b1] = acc4[1] + biasB + gXp[xr1 + c1];
                sG[wn * 256 + c0 * 32 + b2] = acc4[2] + biasA + gXp[xr2 + c0];
                sG[wn * 256 + c1 * 32 + b2] = acc4[3] + biasB + gXp[xr2 + c1];
            }
            __syncthreads();
            // LSTM pointwise
            int b = tid & 31, jj = tid >> 5;
            int j2 = bx * 8 + jj;
            float ii = sG[0 * 256 + jj * 32 + b];
            float ff = sG[1 * 256 + jj * 32 + b];
            float gg = sG[2 * 256 + jj * 32 + b];
            float oo = sG[3 * 256 + jj * 32 + b];
            float si = 1.f / (1.f + expf(-ii));
            float sf = 1.f / (1.f + expf(-ff));
            float so = 1.f / (1.f + expf(-oo));
            float cn = sf * gC[b * H_ + j2] + si * tanhf(gg);
            float hn = so * tanhf(cn);
            gC[b * H_ + j2] = cn;
            gH[b * H_ + j2] = hn;
            size_t hidx = ((size_t)b * S_ + t) * H_ + j2;
            __nv_bfloat16 hb = __float2bfloat16(hn);
            float hf = __bfloat162float(hb);
            __nv_bfloat16 lb = __float2bfloat16(hn - hf);
            gHallH[hidx] = *(unsigned short*)&hb;
            gHallL[hidx] = *(unsigned short*)&lb;
        }
        grid_bar();
    }
}

// ---------------- orchestration ----------------------------------------------
extern "C" void kernel_launch(void* const* d_in, const int* in_sizes, int n_in,
                              void* d_out, int out_size)
{
    const float* features = (const float*)d_in[0];
    const int*   captions = (const int*)  d_in[1];
    const float* emb      = (const float*)d_in[2];
    const float* q_w      = (const float*)d_in[3];
    const float* k_w      = (const float*)d_in[4];
    const float* v_w      = (const float*)d_in[5];
    const float* in_b     = (const float*)d_in[6];
    const float* out_w    = (const float*)d_in[7];
    const float* out_b    = (const float*)d_in[8];
    const float* h0_w     = (const float*)d_in[9];
    const float* h0_b     = (const float*)d_in[10];
    const float* c0_w     = (const float*)d_in[11];
    const float* c0_b     = (const float*)d_in[12];
    const float* w_ih     = (const float*)d_in[13];
    const float* b_ih     = (const float*)d_in[14];
    const float* w_hh     = (const float*)d_in[15];
    const float* b_hh     = (const float*)d_in[16];
    const float* ln_g     = (const float*)d_in[17];
    const float* ln_b2    = (const float*)d_in[18];
    const float* lin_w    = (const float*)d_in[19];
    const float* lin_b    = (const float*)d_in[20];

    float* sc = nullptr;
    cudaGetSymbolAddress((void**)&sc, g_scratch);
    float* gK    = sc + OFF_K;
    float* gV    = sc + OFF_V;
    float* gMean = sc + OFF_MEAN;
    float* gH    = sc + OFF_H;
    float* gC    = sc + OFF_C;
    float* gQ    = sc + OFF_Q;
    float* gCtx  = sc + OFF_CTX;
    float* gO    = sc + OFF_O;
    float* gSc   = sc + OFF_SC;
    float* gXp   = sc + OFF_XP;
    float* gAd   = sc + OFF_AD;
    unsigned short* gFH  = (unsigned short*)(sc + OFF_FH);
    unsigned short* gFL  = (unsigned short*)(sc + OFF_FL);
    unsigned short* gKWH = (unsigned short*)(sc + OFF_KWH);
    unsigned short* gKWL = (unsigned short*)(sc + OFF_KWL);
    unsigned short* gVWH = (unsigned short*)(sc + OFF_VWH);
    unsigned short* gVWL = (unsigned short*)(sc + OFF_VWL);
    unsigned short* gWIH = (unsigned short*)(sc + OFF_WIH);
    unsigned short* gWIL = (unsigned short*)(sc + OFF_WIL);
    unsigned short* gLWH = (unsigned short*)(sc + OFF_LWH);
    unsigned short* gLWL = (unsigned short*)(sc + OFF_LWL);
    unsigned short* gEBH = (unsigned short*)(sc + OFF_EBH);
    unsigned short* gEBL = (unsigned short*)(sc + OFF_EBL);
    unsigned short* gHLH = (unsigned short*)(sc + OFF_HLH);
    unsigned short* gHLL = (unsigned short*)(sc + OFF_HLL);

    float* out   = (float*)d_out;
    float* preds = out;
    const size_t PRED = (size_t)B_ * S_ * V_;
    bool wa = ((size_t)out_size >= PRED + (size_t)B_ * S_ * NF_);
    float* attnb = wa ? (out + PRED) : gAd;

    const int REC_SMEM = 53760 * 4;   // 215,040 B dynamic
    cudaFuncSetAttribute(recurrence_kernel,
                         cudaFuncAttributeMaxDynamicSharedMemorySize, REC_SMEM);
    cudaFuncSetAttribute(mma_gemm_bf16,
                         cudaFuncAttributeMaxDynamicSharedMemorySize, MMA_SMEM_BYTES);

    // ---- one-time bf16 hi/lo splits ----
    split_bf16<<<(B_ * NF_ * ENC_) / 2048, 256>>>(features, gFH, gFL);
    split_bf16<<<(H_ * ENC_) / 2048, 256>>>(k_w, gKWH, gKWL);
    split_bf16<<<(H_ * ENC_) / 2048, 256>>>(v_w, gVWH, gVWL);
    split_bf16<<<(4 * H_ * ED_) / 2048, 256>>>(w_ih, gWIH, gWIL);
    split_bf16<<<(V_ * H_) / 2048, 256>>>(lin_w, gLWH, gLWL);

    // ---- setup (hoisted) ----
    mean_gelu_kernel<<<dim3(ENC_ / 256, B_), 256>>>(features, gMean);
    gemvM32<<<H_ / 8, 256>>>(gMean, h0_w, h0_b, gH, H_, ENC_);
    gemvM32<<<H_ / 8, 256>>>(gMean, c0_w, c0_b, gC, H_, ENC_);
    mma_gemm_bf16<<<dim3(H_ / 64, (B_ * NF_) / 128), 256, MMA_SMEM_BYTES>>>(
        gFH, gFL, ENC_, gKWH, gKWL, in_b + H_,     gK, H_, ENC_);
    mma_gemm_bf16<<<dim3(H_ / 64, (B_ * NF_) / 128), 256, MMA_SMEM_BYTES>>>(
        gFH, gFL, ENC_, gVWH, gVWL, in_b + 2 * H_, gV, H_, ENC_);
    gather_kernel<<<(B_ * S_ * ED_) / 256, 256>>>(emb, captions, gEBH, gEBL);
    mma_gemm_bf16<<<dim3((4 * H_) / 64, (B_ * S_) / 128), 256, MMA_SMEM_BYTES>>>(
        gEBH, gEBL, ED_, gWIH, gWIL, b_ih, gXp, 4 * H_, ED_);

    // ---- recurrence in one persistent kernel ----
    recurrence_kernel<<<NB_, 256, REC_SMEM>>>(
        q_w, in_b, out_w, out_b, w_hh, b_hh, ln_g, ln_b2,
        gK, gV, gXp, gH, gC, gQ, gSc, gCtx, gO, gHLH, gHLL, attnb);

    // ---- batched logits on tensor cores ----
    mma_gemm_bf16<<<dim3(V_ / 64, (B_ * S_) / 128), 256, MMA_SMEM_BYTES>>>(
        gHLH, gHLL, H_, gLWH, gLWL, lin_b, preds, V_, H_);
}